// round 16
// baseline (speedup 1.0000x reference)
#include <cuda_runtime.h>

// ---------------------------------------------------------------------------
// LearnableWaveletTransform, single launch, two block roles:
//   blocks [0, 1032)      : compute valid coefficient regions (proven body)
//   blocks [1032, 3272)   : zero-fill blocks, block-scope decode, contiguous rows
//
//   x: [B=8, S=4096, F=128] f32  ->  out: [6, B, 4096, F] f32
//   slots: [lo3, hi1, hi2, hi3, hi1+hi2+hi3, lo3]
//
//   hi1[s] = sum_{j<8}  Khi[j]  * x[2s-6  + j]      (s < 2051)
//   hi2[s] = sum_{j<22} C2hi[j] * x[4s-18 + j]      (s < 1029)
//   lo3[s] = sum_{j<50} C3lo[j] * x[8s-42 + j]      (s < 518)   (hi3 same taps)
// ---------------------------------------------------------------------------

#define NB     8
#define S0     4096
#define S1     2051
#define S2     1029
#define S3     518
#define F4     32                          // 128 floats = 32 float4
#define SLOTSZ ((size_t)NB * S0 * F4)      // float4 elems per output slot
#define RT     4                           // s positions per thread
#define WPB    4                           // warps per block
#define TS     (WPB * RT)                  // 16 s per block
#define GXV    129                         // ceil(2051/16)
#define NCOMP  (GXV * NB)                  // 1032 compute blocks

// Zero-fill: 64 rows per block, whole blocks per (slot,b) tail.
// tails: s0/3/5 = 3578 rows -> 56 blk ; s1/4 = 2045 -> 32 blk ; s2 = 3067 -> 48 blk
#define NZERO  2240                        // (56+32+48+56+32+56)*8

__constant__ int z_lens[6] = { S3, S1, S2, S3, S1, S3 };
__constant__ int z_bps[6]  = { 56, 32, 48, 56, 32, 56 };          // blocks per (slot,b)
__constant__ int z_bcum[7] = { 0, 448, 704, 1088, 1536, 1792, 2240 }; // per-slot block cum

struct Filt {
    float Klo[8], Khi[8], C2lo[22], C2hi[22], C3lo[50], C3hi[50];
    constexpr Filt()
        : Klo{ 0.23037781330885523f,  0.7148465705525415f,   0.6308807679295904f,
              -0.02798376941698385f, -0.18703481171888114f,  0.030841381835986965f,
               0.032883011666982945f, -0.010597401784997278f },
          Khi{ -0.010597401784997278f, 0.032883011666982945f, 0.030841381835986965f,
                0.18703481171888114f, -0.02798376941698385f, -0.6308807679295904f,
                0.7148465705525415f,  -0.23037781330885523f },
          C2lo{}, C2hi{}, C3lo{}, C3hi{} {
        for (int j = 0; j < 22; ++j) {
            float alo = 0.f, ahi = 0.f;
            for (int u = 0; u < 8; ++u) {
                const int t = j - 2 * u;
                if (t >= 0 && t < 8) { alo += Klo[u] * Klo[t]; ahi += Khi[u] * Klo[t]; }
            }
            C2lo[j] = alo; C2hi[j] = ahi;
        }
        for (int j = 0; j < 50; ++j) {
            float alo = 0.f, ahi = 0.f;
            for (int v = 0; v < 8; ++v) {
                const int t = j - 4 * v;
                if (t >= 0 && t < 22) { alo += Klo[v] * C2lo[t]; ahi += Khi[v] * C2lo[t]; }
            }
            C3lo[j] = alo; C3hi[j] = ahi;
        }
    }
};
__constant__ Filt FF = Filt();

__device__ __forceinline__ void fma4(float4& a, float c, const float4& v) {
    a.x = fmaf(c, v.x, a.x); a.y = fmaf(c, v.y, a.y);
    a.z = fmaf(c, v.z, a.z); a.w = fmaf(c, v.w, a.w);
}
__device__ __forceinline__ void add4(float4& a, const float4& v) {
    a.x += v.x; a.y += v.y; a.z += v.z; a.w += v.w;
}
__device__ __forceinline__ float4 zero4() { return make_float4(0.f, 0.f, 0.f, 0.f); }

__global__ __launch_bounds__(128, 8)
void wavelet_split2_k(const float4* __restrict__ x, float4* __restrict__ out) {
    const int f4 = threadIdx.x;                            // 0..31

    if (blockIdx.x >= NCOMP) {
        // ================= zero-fill block (decode ONCE per block) ==========
        const int zid = blockIdx.x - NCOMP;
        int k = 0;
#pragma unroll
        for (int t = 1; t < 6; ++t)
            if (zid >= z_bcum[t]) k = t;
        const int offb = zid - z_bcum[k];
        const int bps  = z_bps[k];
        const int b    = offb / bps;                       // one division
        const int sbeg = z_lens[k] + (offb - b * bps) * 64 + threadIdx.y * 16;

        float4* __restrict__ dst =
            out + (size_t)k * SLOTSZ + ((size_t)(b * S0 + sbeg)) * F4 + f4;
        const float4 z = zero4();
#pragma unroll
        for (int i = 0; i < 16; ++i) {
            if (sbeg + i < S0)
                __stcs(dst + (size_t)i * F4, z);
        }
        return;
    }

    // ================= compute block (proven valid-only body) =================
    const int b  = blockIdx.x / GXV;
    const int bx = blockIdx.x - b * GXV;
    const int sb = bx * TS + threadIdx.y * RT;

    const float4* __restrict__ xb = x + (size_t)b * (S0 * F4) + f4;
    const size_t obase = ((size_t)(b * S0 + sb)) * F4 + f4;

    float4 hf[RT];
#pragma unroll
    for (int r = 0; r < RT; ++r) hf[r] = zero4();

    // -------- level 3: lo3 -> slots 0,5 ; hi3 -> slot 3 (len 518) --------
    {
        float4 al[RT], ah[RT];
#pragma unroll
        for (int r = 0; r < RT; ++r) { al[r] = zero4(); ah[r] = zero4(); }
        const int base = 8 * sb - 42;                     // span 74
        if (base >= 0 && base + 74 <= S0) {               // interior
#pragma unroll
            for (int k = 0; k < 74; ++k) {
                const float4 v = __ldg(xb + (size_t)(base + k) * F4);
#pragma unroll
                for (int r = 0; r < RT; ++r) {
                    const int j = k - 8 * r;
                    if (j >= 0 && j < 50) {
                        fma4(al[r], FF.C3lo[j], v);
                        fma4(ah[r], FF.C3hi[j], v);
                    }
                }
            }
#pragma unroll
            for (int r = 0; r < RT; ++r) {
                const size_t o = obase + (size_t)r * F4;
                __stcs(out + 0 * SLOTSZ + o, al[r]);
                __stcs(out + 3 * SLOTSZ + o, ah[r]);
                __stcs(out + 5 * SLOTSZ + o, al[r]);
                add4(hf[r], ah[r]);
            }
        } else if (sb < S3) {                             // boundary
#pragma unroll
            for (int k = 0; k < 74; ++k) {
                const int xs = base + k;
                if (xs >= 0 && xs < S0) {
                    const float4 v = __ldg(xb + (size_t)xs * F4);
#pragma unroll
                    for (int r = 0; r < RT; ++r) {
                        const int j = k - 8 * r;
                        if (j >= 0 && j < 50 && (sb + r) < S3) {
                            fma4(al[r], FF.C3lo[j], v);
                            fma4(ah[r], FF.C3hi[j], v);
                        }
                    }
                }
            }
#pragma unroll
            for (int r = 0; r < RT; ++r) {
                if ((sb + r) < S3) {
                    const size_t o = obase + (size_t)r * F4;
                    __stcs(out + 0 * SLOTSZ + o, al[r]);
                    __stcs(out + 3 * SLOTSZ + o, ah[r]);
                    __stcs(out + 5 * SLOTSZ + o, al[r]);
                    add4(hf[r], ah[r]);
                }
            }
        }
    }

    // ---------------- level 2: hi2 -> slot 2 (len 1029) ----------------
    {
        float4 acc[RT];
#pragma unroll
        for (int r = 0; r < RT; ++r) acc[r] = zero4();
        const int base = 4 * sb - 18;                     // span 34
        if (base >= 0 && base + 34 <= S0) {               // interior
#pragma unroll
            for (int k = 0; k < 34; ++k) {
                const float4 v = __ldg(xb + (size_t)(base + k) * F4);
#pragma unroll
                for (int r = 0; r < RT; ++r) {
                    const int j = k - 4 * r;
                    if (j >= 0 && j < 22) fma4(acc[r], FF.C2hi[j], v);
                }
            }
#pragma unroll
            for (int r = 0; r < RT; ++r) {
                __stcs(out + 2 * SLOTSZ + obase + (size_t)r * F4, acc[r]);
                add4(hf[r], acc[r]);
            }
        } else if (sb < S2) {                             // boundary
#pragma unroll
            for (int k = 0; k < 34; ++k) {
                const int xs = base + k;
                if (xs >= 0 && xs < S0) {
                    const float4 v = __ldg(xb + (size_t)xs * F4);
#pragma unroll
                    for (int r = 0; r < RT; ++r) {
                        const int j = k - 4 * r;
                        if (j >= 0 && j < 22 && (sb + r) < S2)
                            fma4(acc[r], FF.C2hi[j], v);
                    }
                }
            }
#pragma unroll
            for (int r = 0; r < RT; ++r) {
                if ((sb + r) < S2) {
                    __stcs(out + 2 * SLOTSZ + obase + (size_t)r * F4, acc[r]);
                    add4(hf[r], acc[r]);
                }
            }
        }
    }

    // ---------------- level 1: hi1 -> slot 1; hf -> slot 4 (len 2051) -------
    {
        float4 acc[RT];
#pragma unroll
        for (int r = 0; r < RT; ++r) acc[r] = zero4();
        const int base = 2 * sb - 6;                      // span 14
        if (base >= 0 && base + 14 <= S0) {               // interior
#pragma unroll
            for (int k = 0; k < 14; ++k) {
                const float4 v = __ldg(xb + (size_t)(base + k) * F4);
#pragma unroll
                for (int r = 0; r < RT; ++r) {
                    const int j = k - 2 * r;
                    if (j >= 0 && j < 8) fma4(acc[r], FF.Khi[j], v);
                }
            }
#pragma unroll
            for (int r = 0; r < RT; ++r) {
                __stcs(out + 1 * SLOTSZ + obase + (size_t)r * F4, acc[r]);
                add4(hf[r], acc[r]);
                __stcs(out + 4 * SLOTSZ + obase + (size_t)r * F4, hf[r]);
            }
        } else if (sb < S1) {                             // boundary
#pragma unroll
            for (int k = 0; k < 14; ++k) {
                const int xs = base + k;
                if (xs >= 0 && xs < S0) {
                    const float4 v = __ldg(xb + (size_t)xs * F4);
#pragma unroll
                    for (int r = 0; r < RT; ++r) {
                        const int j = k - 2 * r;
                        if (j >= 0 && j < 8 && (sb + r) < S1)
                            fma4(acc[r], FF.Khi[j], v);
                    }
                }
            }
#pragma unroll
            for (int r = 0; r < RT; ++r) {
                if ((sb + r) < S1) {
                    __stcs(out + 1 * SLOTSZ + obase + (size_t)r * F4, acc[r]);
                    add4(hf[r], acc[r]);
                    __stcs(out + 4 * SLOTSZ + obase + (size_t)r * F4, hf[r]);
                }
            }
        }
    }
}

extern "C" void kernel_launch(void* const* d_in, const int* in_sizes, int n_in,
                              void* d_out, int out_size) {
    const float4* x = (const float4*)d_in[0];
    float4* out     = (float4*)d_out;

    const dim3 blk(32, WPB);                    // 128 threads
    wavelet_split2_k<<<NCOMP + NZERO, blk>>>(x, out);
}

// round 17
// speedup vs baseline: 1.5882x; 1.5882x over previous
#include <cuda_runtime.h>

// ---------------------------------------------------------------------------
// LearnableWaveletTransform, single launch, two block roles:
//   blocks [0, 1032)      : compute valid coefficient regions (proven body)
//   blocks [1032, 3269)   : dedicated zero-fill blocks for the constant tails
//
//   x: [B=8, S=4096, F=128] f32  ->  out: [6, B, 4096, F] f32
//   slots: [lo3, hi1, hi2, hi3, hi1+hi2+hi3, lo3]
//
//   hi1[s] = sum_{j<8}  Khi[j]  * x[2s-6  + j]      (s < 2051)
//   hi2[s] = sum_{j<22} C2hi[j] * x[4s-18 + j]      (s < 1029)
//   lo3[s] = sum_{j<50} C3lo[j] * x[8s-42 + j]      (s < 518)   (hi3 same taps)
// ---------------------------------------------------------------------------

#define NB     8
#define S0     4096
#define S1     2051
#define S2     1029
#define S3     518
#define F4     32                          // 128 floats = 32 float4
#define SLOTSZ ((size_t)NB * S0 * F4)      // float4 elems per output slot
#define RT     4                           // s positions per thread
#define WPB    4                           // warps per block
#define TS     (WPB * RT)                  // 16 s per block
#define GXV    129                         // ceil(2051/16)
#define NCOMP  (GXV * NB)                  // 1032 compute blocks

// Zero-tail bookkeeping: total tail rows (b-major within slot) = 143128
#define ZROWS_TOTAL 143128
#define ZROWS_BLK   64                     // rows per zero block
#define NZERO       2237                   // ceil(143128/64)

__constant__ int c_lens[6]  = { S3, S1, S2, S3, S1, S3 };
__constant__ int c_tail[6]  = { S0-S3, S0-S1, S0-S2, S0-S3, S0-S1, S0-S3 };
__constant__ int c_cum[7]   = { 0, 28624, 44984, 69520, 98144, 114504, 143128 };

struct Filt {
    float Klo[8], Khi[8], C2lo[22], C2hi[22], C3lo[50], C3hi[50];
    constexpr Filt()
        : Klo{ 0.23037781330885523f,  0.7148465705525415f,   0.6308807679295904f,
              -0.02798376941698385f, -0.18703481171888114f,  0.030841381835986965f,
               0.032883011666982945f, -0.010597401784997278f },
          Khi{ -0.010597401784997278f, 0.032883011666982945f, 0.030841381835986965f,
                0.18703481171888114f, -0.02798376941698385f, -0.6308807679295904f,
                0.7148465705525415f,  -0.23037781330885523f },
          C2lo{}, C2hi{}, C3lo{}, C3hi{} {
        for (int j = 0; j < 22; ++j) {
            float alo = 0.f, ahi = 0.f;
            for (int u = 0; u < 8; ++u) {
                const int t = j - 2 * u;
                if (t >= 0 && t < 8) { alo += Klo[u] * Klo[t]; ahi += Khi[u] * Klo[t]; }
            }
            C2lo[j] = alo; C2hi[j] = ahi;
        }
        for (int j = 0; j < 50; ++j) {
            float alo = 0.f, ahi = 0.f;
            for (int v = 0; v < 8; ++v) {
                const int t = j - 4 * v;
                if (t >= 0 && t < 22) { alo += Klo[v] * C2lo[t]; ahi += Khi[v] * C2lo[t]; }
            }
            C3lo[j] = alo; C3hi[j] = ahi;
        }
    }
};
__constant__ Filt FF = Filt();

__device__ __forceinline__ void fma4(float4& a, float c, const float4& v) {
    a.x = fmaf(c, v.x, a.x); a.y = fmaf(c, v.y, a.y);
    a.z = fmaf(c, v.z, a.z); a.w = fmaf(c, v.w, a.w);
}
__device__ __forceinline__ void add4(float4& a, const float4& v) {
    a.x += v.x; a.y += v.y; a.z += v.z; a.w += v.w;
}
__device__ __forceinline__ float4 zero4() { return make_float4(0.f, 0.f, 0.f, 0.f); }

__global__ __launch_bounds__(128, 8)
void wavelet_split_k(const float4* __restrict__ x, float4* __restrict__ out) {
    const int f4 = threadIdx.x;                            // 0..31

    if (blockIdx.x >= NCOMP) {
        // ================= zero-fill block =================
        const int zid  = blockIdx.x - NCOMP;
        const int rbase = zid * ZROWS_BLK + threadIdx.y * (ZROWS_BLK / WPB);
        const float4 z = zero4();
#pragma unroll
        for (int i = 0; i < ZROWS_BLK / WPB; ++i) {
            const int row = rbase + i;                     // warp-uniform
            if (row < ZROWS_TOTAL) {
                int k = 0;
#pragma unroll
                for (int t = 1; t < 6; ++t)
                    if (row >= c_cum[t]) k = t;
                const int off = row - c_cum[k];
                const int tb  = c_tail[k];
                const int b   = off / tb;                  // warp-uniform div
                const int s   = c_lens[k] + (off - b * tb);
                __stcs(out + (size_t)k * SLOTSZ + ((size_t)(b * S0 + s)) * F4 + f4, z);
            }
        }
        return;
    }

    // ================= compute block (proven valid-only body) =================
    const int b  = blockIdx.x / GXV;
    const int bx = blockIdx.x - b * GXV;
    const int sb = bx * TS + threadIdx.y * RT;

    const float4* __restrict__ xb = x + (size_t)b * (S0 * F4) + f4;
    const size_t obase = ((size_t)(b * S0 + sb)) * F4 + f4;

    float4 hf[RT];
#pragma unroll
    for (int r = 0; r < RT; ++r) hf[r] = zero4();

    // -------- level 3: lo3 -> slots 0,5 ; hi3 -> slot 3 (len 518) --------
    {
        float4 al[RT], ah[RT];
#pragma unroll
        for (int r = 0; r < RT; ++r) { al[r] = zero4(); ah[r] = zero4(); }
        const int base = 8 * sb - 42;                     // span 74
        if (base >= 0 && base + 74 <= S0) {               // interior
#pragma unroll
            for (int k = 0; k < 74; ++k) {
                const float4 v = __ldg(xb + (size_t)(base + k) * F4);
#pragma unroll
                for (int r = 0; r < RT; ++r) {
                    const int j = k - 8 * r;
                    if (j >= 0 && j < 50) {
                        fma4(al[r], FF.C3lo[j], v);
                        fma4(ah[r], FF.C3hi[j], v);
                    }
                }
            }
#pragma unroll
            for (int r = 0; r < RT; ++r) {
                const size_t o = obase + (size_t)r * F4;
                __stcs(out + 0 * SLOTSZ + o, al[r]);
                __stcs(out + 3 * SLOTSZ + o, ah[r]);
                __stcs(out + 5 * SLOTSZ + o, al[r]);
                add4(hf[r], ah[r]);
            }
        } else if (sb < S3) {                             // boundary
#pragma unroll
            for (int k = 0; k < 74; ++k) {
                const int xs = base + k;
                if (xs >= 0 && xs < S0) {
                    const float4 v = __ldg(xb + (size_t)xs * F4);
#pragma unroll
                    for (int r = 0; r < RT; ++r) {
                        const int j = k - 8 * r;
                        if (j >= 0 && j < 50 && (sb + r) < S3) {
                            fma4(al[r], FF.C3lo[j], v);
                            fma4(ah[r], FF.C3hi[j], v);
                        }
                    }
                }
            }
#pragma unroll
            for (int r = 0; r < RT; ++r) {
                if ((sb + r) < S3) {
                    const size_t o = obase + (size_t)r * F4;
                    __stcs(out + 0 * SLOTSZ + o, al[r]);
                    __stcs(out + 3 * SLOTSZ + o, ah[r]);
                    __stcs(out + 5 * SLOTSZ + o, al[r]);
                    add4(hf[r], ah[r]);
                }
            }
        }
    }

    // ---------------- level 2: hi2 -> slot 2 (len 1029) ----------------
    {
        float4 acc[RT];
#pragma unroll
        for (int r = 0; r < RT; ++r) acc[r] = zero4();
        const int base = 4 * sb - 18;                     // span 34
        if (base >= 0 && base + 34 <= S0) {               // interior
#pragma unroll
            for (int k = 0; k < 34; ++k) {
                const float4 v = __ldg(xb + (size_t)(base + k) * F4);
#pragma unroll
                for (int r = 0; r < RT; ++r) {
                    const int j = k - 4 * r;
                    if (j >= 0 && j < 22) fma4(acc[r], FF.C2hi[j], v);
                }
            }
#pragma unroll
            for (int r = 0; r < RT; ++r) {
                __stcs(out + 2 * SLOTSZ + obase + (size_t)r * F4, acc[r]);
                add4(hf[r], acc[r]);
            }
        } else if (sb < S2) {                             // boundary
#pragma unroll
            for (int k = 0; k < 34; ++k) {
                const int xs = base + k;
                if (xs >= 0 && xs < S0) {
                    const float4 v = __ldg(xb + (size_t)xs * F4);
#pragma unroll
                    for (int r = 0; r < RT; ++r) {
                        const int j = k - 4 * r;
                        if (j >= 0 && j < 22 && (sb + r) < S2)
                            fma4(acc[r], FF.C2hi[j], v);
                    }
                }
            }
#pragma unroll
            for (int r = 0; r < RT; ++r) {
                if ((sb + r) < S2) {
                    __stcs(out + 2 * SLOTSZ + obase + (size_t)r * F4, acc[r]);
                    add4(hf[r], acc[r]);
                }
            }
        }
    }

    // ---------------- level 1: hi1 -> slot 1; hf -> slot 4 (len 2051) -------
    {
        float4 acc[RT];
#pragma unroll
        for (int r = 0; r < RT; ++r) acc[r] = zero4();
        const int base = 2 * sb - 6;                      // span 14
        if (base >= 0 && base + 14 <= S0) {               // interior
#pragma unroll
            for (int k = 0; k < 14; ++k) {
                const float4 v = __ldg(xb + (size_t)(base + k) * F4);
#pragma unroll
                for (int r = 0; r < RT; ++r) {
                    const int j = k - 2 * r;
                    if (j >= 0 && j < 8) fma4(acc[r], FF.Khi[j], v);
                }
            }
#pragma unroll
            for (int r = 0; r < RT; ++r) {
                __stcs(out + 1 * SLOTSZ + obase + (size_t)r * F4, acc[r]);
                add4(hf[r], acc[r]);
                __stcs(out + 4 * SLOTSZ + obase + (size_t)r * F4, hf[r]);
            }
        } else if (sb < S1) {                             // boundary
#pragma unroll
            for (int k = 0; k < 14; ++k) {
                const int xs = base + k;
                if (xs >= 0 && xs < S0) {
                    const float4 v = __ldg(xb + (size_t)xs * F4);
#pragma unroll
                    for (int r = 0; r < RT; ++r) {
                        const int j = k - 2 * r;
                        if (j >= 0 && j < 8 && (sb + r) < S1)
                            fma4(acc[r], FF.Khi[j], v);
                    }
                }
            }
#pragma unroll
            for (int r = 0; r < RT; ++r) {
                if ((sb + r) < S1) {
                    __stcs(out + 1 * SLOTSZ + obase + (size_t)r * F4, acc[r]);
                    add4(hf[r], acc[r]);
                    __stcs(out + 4 * SLOTSZ + obase + (size_t)r * F4, hf[r]);
                }
            }
        }
    }
}

extern "C" void kernel_launch(void* const* d_in, const int* in_sizes, int n_in,
                              void* d_out, int out_size) {
    const float4* x = (const float4*)d_in[0];
    float4* out     = (float4*)d_out;

    const dim3 blk(32, WPB);                    // 128 threads
    wavelet_split_k<<<NCOMP + NZERO, blk>>>(x, out);
}